// round 2
// baseline (speedup 1.0000x reference)
#include <cuda_runtime.h>

#define BATCH 65536
#define THR_A 128
#define NBLK_A (BATCH / THR_A)
#define THR_B 256
#define NBLK_B (BATCH / THR_B)

// Scratch (sanctioned __device__ globals, no runtime allocation)
__device__ float g_Wa[128];            // interleaved: [2j]=Wa1[j], [2j+1]=Wa2[j]
__device__ float g_x[64 * BATCH];      // fc1 output, TRANSPOSED [j][i] for coalesced loads

__device__ __forceinline__ float lrelu(float v) { return v > 0.f ? v : 0.01f * v; }

// ---------------------------------------------------------------------------
// Precompute Wa1 = W @ a[:64], Wa2 = W @ a[64:]  (collapses the 10x64x64 GEMM)
// ---------------------------------------------------------------------------
__global__ void k_pre(const float* __restrict__ W, const float* __restrict__ a)
{
    int k = threadIdx.x;  // 64 threads
    float s1 = 0.f, s2 = 0.f;
    #pragma unroll 16
    for (int j = 0; j < 64; j++) {
        float w = W[k * 64 + j];
        s1 = fmaf(w, a[j], s1);
        s2 = fmaf(w, a[64 + j], s2);
    }
    g_Wa[2 * k]     = s1;
    g_Wa[2 * k + 1] = s2;
}

// ---------------------------------------------------------------------------
// Kernel A: attention path + fc1 (one thread per batch element)
// Writes x = relu(obs_comb @ w_fc1 + b_fc1) transposed into g_x.
// ---------------------------------------------------------------------------
__global__ __launch_bounds__(THR_A) void k_att(
    const float* __restrict__ obs,
    const float* __restrict__ w_in0, const float* __restrict__ b_in0,
    const float* __restrict__ w_in1, const float* __restrict__ b_in1,
    const float* __restrict__ w_in2, const float* __restrict__ b_in2,
    const float* __restrict__ w_o1,  const float* __restrict__ b_o1,
    const float* __restrict__ w_o2,  const float* __restrict__ b_o2,
    const float* __restrict__ w_o3,  const float* __restrict__ b_o3,
    const float* __restrict__ w_fc1, const float* __restrict__ b_fc1)
{
    __shared__ __align__(16) float s_wint[3 * 64 * 8];  // transposed [sel][j][f]
    __shared__ float s_bin[3 * 64];
    __shared__ __align__(8)  float s_wa[128];
    __shared__ __align__(16) float s_wo1[10 * 32];
    __shared__ float s_bo1[32];
    __shared__ __align__(16) float s_wo2[32 * 16];
    __shared__ float s_bo2[16];
    __shared__ float s_wo3[16];
    __shared__ float s_bo3v[1];
    __shared__ __align__(16) float s_wfc1[90 * 64];
    __shared__ float s_bfc1[64];

    const int tid = threadIdx.x;

    for (int idx = tid; idx < 1536; idx += THR_A) {
        int sel = idx >> 9, rem = idx & 511;
        int j = rem >> 3, f = rem & 7;
        const float* w = (sel == 0) ? w_in0 : ((sel == 1) ? w_in1 : w_in2);
        s_wint[idx] = w[f * 64 + j];
    }
    for (int idx = tid; idx < 192; idx += THR_A)
        s_bin[idx] = (idx < 64) ? b_in0[idx] : ((idx < 128) ? b_in1[idx - 64] : b_in2[idx - 128]);
    if (tid < 128) s_wa[tid] = g_Wa[tid];
    for (int idx = tid; idx < 320; idx += THR_A) s_wo1[idx] = w_o1[idx];
    if (tid < 32) s_bo1[tid] = b_o1[tid];
    for (int idx = tid; idx < 512; idx += THR_A) s_wo2[idx] = w_o2[idx];
    if (tid < 16) { s_bo2[tid] = b_o2[tid]; s_wo3[tid] = w_o3[tid]; }
    if (tid == 0) s_bo3v[0] = b_o3[0];
    for (int idx = tid; idx < 5760; idx += THR_A) s_wfc1[idx] = w_fc1[idx];
    if (tid < 64) s_bfc1[tid] = b_fc1[tid];
    __syncthreads();

    const int i = blockIdx.x * THR_A + tid;
    const float* orow = obs + (size_t)i * 85;

    // fc1 accumulators (register resident, fused with the single obs pass)
    float acc[64];
    #pragma unroll
    for (int j = 0; j < 64; j++) acc[j] = s_bfc1[j];

    float wh1[10], wh2[10];  // small, may live in local — low traffic, OK

    for (int t = 0; t < 10; t++) {
        int sel = (t < 5) ? 0 : ((t < 9) ? 1 : 2);
        const float* wt = s_wint + sel * 512;
        const float* bb = s_bin + sel * 64;
        int base = 4 + 8 * t;

        float ov[8];
        #pragma unroll
        for (int f = 0; f < 8; f++) {
            int k = base + f; if (k >= 80) k -= 80;   // wrap only at t==9
            ov[f] = orow[k];
        }

        // h_t = leaky(obs_in[t] @ w_sel + b_sel); wh = h_t . Wa{1,2}
        float s1 = 0.f, s2 = 0.f;
        #pragma unroll
        for (int j = 0; j < 64; j++) {
            const float4* wj = (const float4*)(wt + j * 8);
            float4 w0 = wj[0], w1 = wj[1];
            float hv = bb[j];
            hv = fmaf(ov[0], w0.x, hv); hv = fmaf(ov[1], w0.y, hv);
            hv = fmaf(ov[2], w0.z, hv); hv = fmaf(ov[3], w0.w, hv);
            hv = fmaf(ov[4], w1.x, hv); hv = fmaf(ov[5], w1.y, hv);
            hv = fmaf(ov[6], w1.z, hv); hv = fmaf(ov[7], w1.w, hv);
            hv = lrelu(hv);
            float2 wa = *(const float2*)(s_wa + 2 * j);
            s1 = fmaf(hv, wa.x, s1);
            s2 = fmaf(hv, wa.y, s2);
        }
        wh1[t] = s1; wh2[t] = s2;

        // fc1 contribution of these same obs values (obs read exactly once)
        #pragma unroll
        for (int f = 0; f < 8; f++) {
            int k = base + f; if (k >= 80) k -= 80;
            const float* wr = s_wfc1 + k * 64;
            float v = ov[f];
            #pragma unroll
            for (int j = 0; j < 64; j++) acc[j] = fmaf(v, wr[j], acc[j]);
        }
    }

    // att1 softmax stats (rows u=5..9 over cols 0..4)
    float m1[5], iz1[5];
    #pragma unroll
    for (int u = 0; u < 5; u++) {
        float e0 = lrelu(wh1[5 + u] + wh2[0]);
        float e1 = lrelu(wh1[5 + u] + wh2[1]);
        float e2 = lrelu(wh1[5 + u] + wh2[2]);
        float e3 = lrelu(wh1[5 + u] + wh2[3]);
        float e4 = lrelu(wh1[5 + u] + wh2[4]);
        float m = fmaxf(fmaxf(fmaxf(e0, e1), fmaxf(e2, e3)), e4);
        float z = __expf(e0 - m) + __expf(e1 - m) + __expf(e2 - m)
                + __expf(e3 - m) + __expf(e4 - m);
        m1[u] = m; iz1[u] = 1.f / z;
    }

    float hp3[5];
    #pragma unroll
    for (int r = 0; r < 5; r++) {
        float att[10];
        float ev[5]; float m = -1e30f;
        #pragma unroll
        for (int c = 0; c < 5; c++) { ev[c] = lrelu(wh1[r] + wh2[5 + c]); m = fmaxf(m, ev[c]); }
        float z = 0.f;
        #pragma unroll
        for (int c = 0; c < 5; c++) { ev[c] = __expf(ev[c] - m); z += ev[c]; }
        float izr = 1.f / z;
        #pragma unroll
        for (int c = 0; c < 5; c++) att[c] = ev[c] * izr;
        #pragma unroll
        for (int u = 0; u < 5; u++)
            att[5 + u] = __expf(lrelu(wh1[5 + u] + wh2[r]) - m1[u]) * iz1[u];

        float hp1[32];
        #pragma unroll
        for (int j = 0; j < 32; j++) hp1[j] = s_bo1[j];
        #pragma unroll
        for (int c = 0; c < 10; c++) {
            float av = att[c];
            const float* wr = s_wo1 + c * 32;
            #pragma unroll
            for (int j = 0; j < 32; j++) hp1[j] = fmaf(av, wr[j], hp1[j]);
        }
        float hp2[16];
        #pragma unroll
        for (int j2 = 0; j2 < 16; j2++) hp2[j2] = s_bo2[j2];
        #pragma unroll
        for (int j = 0; j < 32; j++) {
            float v = lrelu(hp1[j]);
            const float* wr = s_wo2 + j * 16;
            #pragma unroll
            for (int j2 = 0; j2 < 16; j2++) hp2[j2] = fmaf(v, wr[j2], hp2[j2]);
        }
        float s = s_bo3v[0];
        #pragma unroll
        for (int j2 = 0; j2 < 16; j2++) s = fmaf(lrelu(hp2[j2]), s_wo3[j2], s);
        hp3[r] = lrelu(s);
    }

    // softmax over hp3 -> obs_out
    float m = hp3[0];
    #pragma unroll
    for (int r = 1; r < 5; r++) m = fmaxf(m, hp3[r]);
    float z = 0.f; float oo[5];
    #pragma unroll
    for (int r = 0; r < 5; r++) { oo[r] = __expf(hp3[r] - m); z += oo[r]; }
    float iz = 1.f / z;

    // fc1 tail: obs[80..84] then obs_out[0..4]
    #pragma unroll
    for (int k = 80; k < 85; k++) {
        float v = orow[k];
        const float* wr = s_wfc1 + k * 64;
        #pragma unroll
        for (int j = 0; j < 64; j++) acc[j] = fmaf(v, wr[j], acc[j]);
    }
    #pragma unroll
    for (int u = 0; u < 5; u++) {
        float v = oo[u] * iz;
        const float* wr = s_wfc1 + (85 + u) * 64;
        #pragma unroll
        for (int j = 0; j < 64; j++) acc[j] = fmaf(v, wr[j], acc[j]);
    }

    // relu + transposed store (coalesced per j)
    #pragma unroll
    for (int j = 0; j < 64; j++)
        g_x[(size_t)j * BATCH + i] = fmaxf(acc[j], 0.f);
}

// ---------------------------------------------------------------------------
// Kernel B: GRU cell + q head. Per-gate-j formulation: 6 scalar dot
// accumulators per j, no cross-j register arrays needed.
// ---------------------------------------------------------------------------
__global__ __launch_bounds__(THR_B) void k_gru(
    const float* __restrict__ hidden,
    const float* __restrict__ w_ih, const float* __restrict__ w_hh,
    const float* __restrict__ b_ih, const float* __restrict__ b_hh,
    const float* __restrict__ w_fc2, const float* __restrict__ b_fc2,
    float* __restrict__ out)
{
    extern __shared__ float sm[];
    float* s_wih  = sm;              // 12288
    float* s_whh  = sm + 12288;      // 12288
    float* s_bih  = sm + 24576;      // 192
    float* s_bhh  = sm + 24768;      // 192
    float* s_wfc2 = sm + 24960;      // 320
    float* s_bfc2 = sm + 25280;      // 8 (5 used)
    float* s_hst  = sm + 25288;      // 256*65 staging (also holds h_in[j])

    const int tid = threadIdx.x;
    {
        const float4* src = (const float4*)w_ih; float4* dst = (float4*)s_wih;
        for (int idx = tid; idx < 3072; idx += THR_B) dst[idx] = src[idx];
        src = (const float4*)w_hh; dst = (float4*)s_whh;
        for (int idx = tid; idx < 3072; idx += THR_B) dst[idx] = src[idx];
    }
    for (int idx = tid; idx < 192; idx += THR_B) { s_bih[idx] = b_ih[idx]; s_bhh[idx] = b_hh[idx]; }
    for (int idx = tid; idx < 320; idx += THR_B) s_wfc2[idx] = w_fc2[idx];
    if (tid < 5) s_bfc2[tid] = b_fc2[tid];
    __syncthreads();

    const int i = blockIdx.x * THR_B + tid;
    const int hbase = tid * 65;

    float x[64], h[64];
    #pragma unroll
    for (int k = 0; k < 64; k++) x[k] = g_x[(size_t)k * BATCH + i];  // coalesced
    {
        const float4* hp4 = (const float4*)(hidden + (size_t)i * 64);
        #pragma unroll
        for (int k4 = 0; k4 < 16; k4++) {
            float4 v = hp4[k4];
            h[4 * k4]     = v.x; h[4 * k4 + 1] = v.y;
            h[4 * k4 + 2] = v.z; h[4 * k4 + 3] = v.w;
            s_hst[hbase + 4 * k4]     = v.x; s_hst[hbase + 4 * k4 + 1] = v.y;
            s_hst[hbase + 4 * k4 + 2] = v.z; s_hst[hbase + 4 * k4 + 3] = v.w;
        }
    }

    float q[5];
    #pragma unroll
    for (int a5 = 0; a5 < 5; a5++) q[a5] = s_bfc2[a5];

    for (int j = 0; j < 64; j++) {
        const float* wir = s_wih + j * 64;
        const float* wiz = wir + 64 * 64;
        const float* win = wir + 128 * 64;
        const float* whr = s_whh + j * 64;
        const float* whz = whr + 64 * 64;
        const float* whn = whr + 128 * 64;
        float ar = s_bih[j], az = s_bih[64 + j], an = s_bih[128 + j];
        float br = s_bhh[j], bz = s_bhh[64 + j], bn = s_bhh[128 + j];
        #pragma unroll
        for (int k = 0; k < 64; k++) {
            float xv = x[k], hv = h[k];
            ar = fmaf(xv, wir[k], ar);
            az = fmaf(xv, wiz[k], az);
            an = fmaf(xv, win[k], an);
            br = fmaf(hv, whr[k], br);
            bz = fmaf(hv, whz[k], bz);
            bn = fmaf(hv, whn[k], bn);
        }
        float r  = 1.f / (1.f + __expf(-(ar + br)));
        float zz = 1.f / (1.f + __expf(-(az + bz)));
        float n  = tanhf(fmaf(r, bn, an));
        float hj = s_hst[hbase + j];               // h_in[j] (avoids dyn reg index)
        float hnew = fmaf(zz, hj - n, n);          // (1-z)*n + z*h
        s_hst[hbase + j] = hnew;                   // stage for coalesced store
        #pragma unroll
        for (int a5 = 0; a5 < 5; a5++) q[a5] = fmaf(hnew, s_wfc2[j * 5 + a5], q[a5]);
    }

    #pragma unroll
    for (int a5 = 0; a5 < 5; a5++) out[(size_t)i * 5 + a5] = q[a5];

    __syncthreads();
    // coalesced h writeback: this block owns out[B*5 + blk*256*64 ...)
    float* dst = out + (size_t)BATCH * 5 + (size_t)blockIdx.x * THR_B * 64;
    for (int idx = tid; idx < THR_B * 64; idx += THR_B) {
        int il = idx >> 6, j = idx & 63;
        dst[idx] = s_hst[il * 65 + j];
    }
}

// ---------------------------------------------------------------------------
extern "C" void kernel_launch(void* const* d_in, const int* in_sizes, int n_in,
                              void* d_out, int out_size)
{
    (void)in_sizes; (void)n_in; (void)out_size;
    const float* obs    = (const float*)d_in[0];
    const float* hidden = (const float*)d_in[1];
    const float* w_in0  = (const float*)d_in[2];
    const float* b_in0  = (const float*)d_in[3];
    const float* w_in1  = (const float*)d_in[4];
    const float* b_in1  = (const float*)d_in[5];
    const float* w_in2  = (const float*)d_in[6];
    const float* b_in2  = (const float*)d_in[7];
    const float* W      = (const float*)d_in[8];
    const float* a      = (const float*)d_in[9];
    const float* w_o1   = (const float*)d_in[10];
    const float* b_o1   = (const float*)d_in[11];
    const float* w_o2   = (const float*)d_in[12];
    const float* b_o2   = (const float*)d_in[13];
    const float* w_o3   = (const float*)d_in[14];
    const float* b_o3   = (const float*)d_in[15];
    const float* w_fc1  = (const float*)d_in[16];
    const float* b_fc1  = (const float*)d_in[17];
    const float* w_ih   = (const float*)d_in[18];
    const float* w_hh   = (const float*)d_in[19];
    const float* b_ih   = (const float*)d_in[20];
    const float* b_hh   = (const float*)d_in[21];
    const float* w_fc2  = (const float*)d_in[22];
    const float* b_fc2  = (const float*)d_in[23];

    const int smemB = (25288 + 256 * 65) * (int)sizeof(float);  // ~167.7 KB
    cudaFuncSetAttribute(k_gru, cudaFuncAttributeMaxDynamicSharedMemorySize, smemB);

    k_pre<<<1, 64>>>(W, a);
    k_att<<<NBLK_A, THR_A>>>(obs,
                             w_in0, b_in0, w_in1, b_in1, w_in2, b_in2,
                             w_o1, b_o1, w_o2, b_o2, w_o3, b_o3,
                             w_fc1, b_fc1);
    k_gru<<<NBLK_B, THR_B, smemB>>>(hidden, w_ih, w_hh, b_ih, b_hh,
                                    w_fc2, b_fc2, (float*)d_out);
}

// round 3
// speedup vs baseline: 1.2217x; 1.2217x over previous
#include <cuda_runtime.h>

#define BATCH 65536
#define THR_A 128
#define NBLK_A (BATCH / THR_A)
#define THR_B 256
#define NBLK_B (BATCH / THR_B)

typedef unsigned long long ull;

// fc1 output, pre-paired: g_x2[j2*BATCH + i] = (x[2*j2], x[2*j2+1])
__device__ float2 g_x2[32 * BATCH];

__device__ __forceinline__ float lrelu(float v) { return v > 0.f ? v : 0.01f * v; }

__device__ __forceinline__ ull pack2(float lo, float hi) {
    ull r; asm("mov.b64 %0, {%1,%2};" : "=l"(r) : "f"(lo), "f"(hi)); return r;
}
__device__ __forceinline__ void unpack2(ull v, float& lo, float& hi) {
    asm("mov.b64 {%0,%1}, %2;" : "=f"(lo), "=f"(hi) : "l"(v));
}
__device__ __forceinline__ void ffma2(ull& d, ull a, ull b) {
    asm("fma.rn.f32x2 %0, %1, %2, %0;" : "+l"(d) : "l"(a), "l"(b));
}
__device__ __forceinline__ float sum2(ull v) {
    float lo, hi; unpack2(v, lo, hi); return lo + hi;
}
__device__ __forceinline__ float sigm(float x) { return 1.f / (1.f + __expf(-x)); }

// ---------------------------------------------------------------------------
// Kernel A smem partition (floats)
// ---------------------------------------------------------------------------
#define SOBS   0        // 128*85 = 10880   (prologue: aliases W staging 4096)
#define SWFC1  10880    // 5760
#define SWINT  16640    // 1536  transposed [sel][j][f]
#define SWO1   18176    // 320
#define SWO2   18496    // 512
#define SBIN   19008    // 192
#define SWA    19200    // 128 interleaved (Wa1[j],Wa2[j])
#define SBO1   19328    // 32
#define SBO2   19360    // 16
#define SWO3   19376    // 16
#define SBFC1  19392    // 64
#define SBO3   19456    // 1
#define SM_A_FLOATS 19460

__global__ __launch_bounds__(THR_A) void k_att(
    const float* __restrict__ obs,
    const float* __restrict__ w_in0, const float* __restrict__ b_in0,
    const float* __restrict__ w_in1, const float* __restrict__ b_in1,
    const float* __restrict__ w_in2, const float* __restrict__ b_in2,
    const float* __restrict__ W,     const float* __restrict__ a,
    const float* __restrict__ w_o1,  const float* __restrict__ b_o1,
    const float* __restrict__ w_o2,  const float* __restrict__ b_o2,
    const float* __restrict__ w_o3,  const float* __restrict__ b_o3,
    const float* __restrict__ w_fc1, const float* __restrict__ b_fc1)
{
    extern __shared__ float sm[];
    const int tid = threadIdx.x;

    // ---- Prologue 0: Wa = W @ a (W staged into the obs region, then freed) ----
    {
        float4* dW = (float4*)(sm + SOBS);
        const float4* sW = (const float4*)W;
        for (int idx = tid; idx < 1024; idx += THR_A) dW[idx] = sW[idx];
        __syncthreads();
        if (tid < 64) {
            const float* wr = sm + SOBS + tid * 64;
            float s1 = 0.f, s2 = 0.f;
            #pragma unroll 16
            for (int j = 0; j < 64; j++) {
                float w = wr[j];
                s1 = fmaf(w, a[j], s1);
                s2 = fmaf(w, a[64 + j], s2);
            }
            sm[SWA + 2 * tid]     = s1;
            sm[SWA + 2 * tid + 1] = s2;
        }
        __syncthreads();
    }

    // ---- Prologue 1: weights + obs staging ----
    for (int idx = tid; idx < 1536; idx += THR_A) {
        int sel = idx >> 9, rem = idx & 511;
        int j = rem >> 3, f = rem & 7;
        const float* w = (sel == 0) ? w_in0 : ((sel == 1) ? w_in1 : w_in2);
        sm[SWINT + idx] = w[f * 64 + j];
    }
    for (int idx = tid; idx < 192; idx += THR_A)
        sm[SBIN + idx] = (idx < 64) ? b_in0[idx] : ((idx < 128) ? b_in1[idx - 64] : b_in2[idx - 128]);
    for (int idx = tid; idx < 320; idx += THR_A) sm[SWO1 + idx] = w_o1[idx];
    if (tid < 32) sm[SBO1 + tid] = b_o1[tid];
    for (int idx = tid; idx < 512; idx += THR_A) sm[SWO2 + idx] = w_o2[idx];
    if (tid < 16) { sm[SBO2 + tid] = b_o2[tid]; sm[SWO3 + tid] = w_o3[tid]; }
    if (tid == 0) sm[SBO3] = b_o3[0];
    for (int idx = tid; idx < 5760; idx += THR_A) sm[SWFC1 + idx] = w_fc1[idx];
    if (tid < 64) sm[SBFC1 + tid] = b_fc1[tid];
    {   // coalesced obs block copy (128 rows * 85 floats = 2720 float4)
        const float4* src = (const float4*)(obs + (size_t)blockIdx.x * THR_A * 85);
        float4* dst = (float4*)(sm + SOBS);
        for (int idx = tid; idx < 2720; idx += THR_A) dst[idx] = src[idx];
    }
    __syncthreads();

    const int i = blockIdx.x * THR_A + tid;
    const float* so = sm + SOBS + tid * 85;   // gcd(85,32)=1 -> conflict-free

    // ================= Phase 1: attention path -> obs_out =================
    float wh1[10], wh2[10];
    const ull* wa2 = (const ull*)(sm + SWA);

    for (int t = 0; t < 10; t++) {
        const int sel = (t < 5) ? 0 : ((t < 9) ? 1 : 2);
        const float* wt = sm + SWINT + sel * 512;
        const float* bb = sm + SBIN + sel * 64;
        const int base = 4 + 8 * t;

        float ov[8];
        #pragma unroll
        for (int f = 0; f < 8; f++) {
            int k = base + f; if (k >= 80) k -= 80;
            ov[f] = so[k];
        }
        ull ovp[4];
        #pragma unroll
        for (int m = 0; m < 4; m++) ovp[m] = pack2(ov[2 * m], ov[2 * m + 1]);

        ull s12 = pack2(0.f, 0.f);
        #pragma unroll 8
        for (int j = 0; j < 64; j++) {
            const ull* wj = (const ull*)(wt + j * 8);
            ull h2 = pack2(bb[j], 0.f);
            ffma2(h2, ovp[0], wj[0]);
            ffma2(h2, ovp[1], wj[1]);
            ffma2(h2, ovp[2], wj[2]);
            ffma2(h2, ovp[3], wj[3]);
            float hv = lrelu(sum2(h2));
            ffma2(s12, pack2(hv, hv), wa2[j]);
        }
        unpack2(s12, wh1[t], wh2[t]);
    }

    // att1 softmax stats (rows u=5..9 over cols 0..4)
    float m1[5], iz1[5];
    #pragma unroll
    for (int u = 0; u < 5; u++) {
        float e0 = lrelu(wh1[5 + u] + wh2[0]);
        float e1 = lrelu(wh1[5 + u] + wh2[1]);
        float e2 = lrelu(wh1[5 + u] + wh2[2]);
        float e3 = lrelu(wh1[5 + u] + wh2[3]);
        float e4 = lrelu(wh1[5 + u] + wh2[4]);
        float m = fmaxf(fmaxf(fmaxf(e0, e1), fmaxf(e2, e3)), e4);
        float z = __expf(e0 - m) + __expf(e1 - m) + __expf(e2 - m)
                + __expf(e3 - m) + __expf(e4 - m);
        m1[u] = m; iz1[u] = 1.f / z;
    }

    float hp3[5];
    #pragma unroll
    for (int r = 0; r < 5; r++) {
        float att[10];
        float ev[5]; float m = -1e30f;
        #pragma unroll
        for (int c = 0; c < 5; c++) { ev[c] = lrelu(wh1[r] + wh2[5 + c]); m = fmaxf(m, ev[c]); }
        float z = 0.f;
        #pragma unroll
        for (int c = 0; c < 5; c++) { ev[c] = __expf(ev[c] - m); z += ev[c]; }
        float izr = 1.f / z;
        #pragma unroll
        for (int c = 0; c < 5; c++) att[c] = ev[c] * izr;
        #pragma unroll
        for (int u = 0; u < 5; u++)
            att[5 + u] = __expf(lrelu(wh1[5 + u] + wh2[r]) - m1[u]) * iz1[u];

        ull hp1[16];
        {
            const ull* b1 = (const ull*)(sm + SBO1);
            #pragma unroll
            for (int jj = 0; jj < 16; jj++) hp1[jj] = b1[jj];
        }
        #pragma unroll
        for (int c = 0; c < 10; c++) {
            ull av = pack2(att[c], att[c]);
            const ull* wr = (const ull*)(sm + SWO1 + c * 32);
            #pragma unroll
            for (int jj = 0; jj < 16; jj++) ffma2(hp1[jj], av, wr[jj]);
        }
        ull hp2[8];
        {
            const ull* b2 = (const ull*)(sm + SBO2);
            #pragma unroll
            for (int j2 = 0; j2 < 8; j2++) hp2[j2] = b2[j2];
        }
        #pragma unroll
        for (int jj = 0; jj < 16; jj++) {
            float lo, hi; unpack2(hp1[jj], lo, hi);
            {
                float v = lrelu(lo); ull vv = pack2(v, v);
                const ull* wr = (const ull*)(sm + SWO2 + (2 * jj) * 16);
                #pragma unroll
                for (int j2 = 0; j2 < 8; j2++) ffma2(hp2[j2], vv, wr[j2]);
            }
            {
                float v = lrelu(hi); ull vv = pack2(v, v);
                const ull* wr = (const ull*)(sm + SWO2 + (2 * jj + 1) * 16);
                #pragma unroll
                for (int j2 = 0; j2 < 8; j2++) ffma2(hp2[j2], vv, wr[j2]);
            }
        }
        float s = sm[SBO3];
        #pragma unroll
        for (int j2 = 0; j2 < 8; j2++) {
            float lo, hi; unpack2(hp2[j2], lo, hi);
            s = fmaf(lrelu(lo), sm[SWO3 + 2 * j2], s);
            s = fmaf(lrelu(hi), sm[SWO3 + 2 * j2 + 1], s);
        }
        hp3[r] = lrelu(s);
    }

    // softmax(hp3) -> normalized obs_out
    float oo[5];
    {
        float m = hp3[0];
        #pragma unroll
        for (int r = 1; r < 5; r++) m = fmaxf(m, hp3[r]);
        float z = 0.f;
        #pragma unroll
        for (int r = 0; r < 5; r++) { oo[r] = __expf(hp3[r] - m); z += oo[r]; }
        float iz = 1.f / z;
        #pragma unroll
        for (int r = 0; r < 5; r++) oo[r] *= iz;
    }

    // ================= Phase 2: fc1 (packed accumulators) =================
    ull acc[32];
    {
        const ull* bf = (const ull*)(sm + SBFC1);
        #pragma unroll
        for (int jj = 0; jj < 32; jj++) acc[jj] = bf[jj];
    }
    #pragma unroll 1
    for (int k = 0; k < 85; k++) {
        float v = so[k];
        ull vv = pack2(v, v);
        const ull* wr = (const ull*)(sm + SWFC1 + k * 64);
        #pragma unroll
        for (int jj = 0; jj < 32; jj++) ffma2(acc[jj], vv, wr[jj]);
    }
    #pragma unroll
    for (int u = 0; u < 5; u++) {
        ull vv = pack2(oo[u], oo[u]);
        const ull* wr = (const ull*)(sm + SWFC1 + (85 + u) * 64);
        #pragma unroll
        for (int jj = 0; jj < 32; jj++) ffma2(acc[jj], vv, wr[jj]);
    }

    // relu + paired transposed store (coalesced float2 per j-pair)
    #pragma unroll
    for (int jj = 0; jj < 32; jj++) {
        float lo, hi; unpack2(acc[jj], lo, hi);
        g_x2[(size_t)jj * BATCH + i] = make_float2(fmaxf(lo, 0.f), fmaxf(hi, 0.f));
    }
}

// ---------------------------------------------------------------------------
// Kernel B: GRU + q head, fully f32x2-packed dot products.
// ---------------------------------------------------------------------------
#define GWIH   0        // 12288
#define GWHH   12288    // 12288
#define GBIH   24576    // 192
#define GBHH   24768    // 192
#define GWFC2  24960    // 384 (padded stride 6)
#define GBFC2  25344    // 8
#define GHST   25352    // 256*65 = 16640
#define SM_B_FLOATS (GHST + THR_B * 65)

__global__ __launch_bounds__(THR_B) void k_gru(
    const float* __restrict__ hidden,
    const float* __restrict__ w_ih, const float* __restrict__ w_hh,
    const float* __restrict__ b_ih, const float* __restrict__ b_hh,
    const float* __restrict__ w_fc2, const float* __restrict__ b_fc2,
    float* __restrict__ out)
{
    extern __shared__ float sm[];
    const int tid = threadIdx.x;

    {
        const float4* src = (const float4*)w_ih; float4* dst = (float4*)(sm + GWIH);
        for (int idx = tid; idx < 3072; idx += THR_B) dst[idx] = src[idx];
        src = (const float4*)w_hh; dst = (float4*)(sm + GWHH);
        for (int idx = tid; idx < 3072; idx += THR_B) dst[idx] = src[idx];
    }
    for (int idx = tid; idx < 192; idx += THR_B) { sm[GBIH + idx] = b_ih[idx]; sm[GBHH + idx] = b_hh[idx]; }
    for (int idx = tid; idx < 320; idx += THR_B) {
        int j = idx / 5, a5 = idx % 5;
        sm[GWFC2 + j * 6 + a5] = w_fc2[idx];
    }
    if (tid < 5) sm[GBFC2 + tid] = b_fc2[tid];
    __syncthreads();

    const int i = blockIdx.x * THR_B + tid;
    const int hbase = GHST + tid * 65;

    ull xw[32], hw[32];
    #pragma unroll
    for (int m = 0; m < 32; m++) {
        float2 v = g_x2[(size_t)m * BATCH + i];   // coalesced
        xw[m] = pack2(v.x, v.y);
    }
    {
        const float4* hp4 = (const float4*)(hidden + (size_t)i * 64);
        #pragma unroll
        for (int m4 = 0; m4 < 16; m4++) {
            float4 v = hp4[m4];
            hw[2 * m4]     = pack2(v.x, v.y);
            hw[2 * m4 + 1] = pack2(v.z, v.w);
            sm[hbase + 4 * m4]     = v.x; sm[hbase + 4 * m4 + 1] = v.y;
            sm[hbase + 4 * m4 + 2] = v.z; sm[hbase + 4 * m4 + 3] = v.w;
        }
    }

    ull q01 = pack2(sm[GBFC2 + 0], sm[GBFC2 + 1]);
    ull q23 = pack2(sm[GBFC2 + 2], sm[GBFC2 + 3]);
    float q4 = sm[GBFC2 + 4];

    #pragma unroll 1
    for (int j = 0; j < 64; j++) {
        const ulonglong2* wir = (const ulonglong2*)(sm + GWIH + j * 64);
        const ulonglong2* wiz = wir + 1024;   // +64*64 floats
        const ulonglong2* win = wir + 2048;
        const ulonglong2* whr = (const ulonglong2*)(sm + GWHH + j * 64);
        const ulonglong2* whz = whr + 1024;
        const ulonglong2* whn = whr + 2048;

        ull pr = pack2(sm[GBIH + j], 0.f);
        ull pz = pack2(sm[GBIH + 64 + j], 0.f);
        ull pn = pack2(sm[GBIH + 128 + j], 0.f);
        ull qr = pack2(sm[GBHH + j], 0.f);
        ull qz = pack2(sm[GBHH + 64 + j], 0.f);
        ull qn = pack2(sm[GBHH + 128 + j], 0.f);

        #pragma unroll
        for (int m2 = 0; m2 < 16; m2++) {
            ulonglong2 w;
            w = wir[m2]; ffma2(pr, xw[2 * m2], w.x); ffma2(pr, xw[2 * m2 + 1], w.y);
            w = wiz[m2]; ffma2(pz, xw[2 * m2], w.x); ffma2(pz, xw[2 * m2 + 1], w.y);
            w = win[m2]; ffma2(pn, xw[2 * m2], w.x); ffma2(pn, xw[2 * m2 + 1], w.y);
            w = whr[m2]; ffma2(qr, hw[2 * m2], w.x); ffma2(qr, hw[2 * m2 + 1], w.y);
            w = whz[m2]; ffma2(qz, hw[2 * m2], w.x); ffma2(qz, hw[2 * m2 + 1], w.y);
            w = whn[m2]; ffma2(qn, hw[2 * m2], w.x); ffma2(qn, hw[2 * m2 + 1], w.y);
        }

        float ar = sum2(pr), az = sum2(pz), an = sum2(pn);
        float br = sum2(qr), bz = sum2(qz), bn = sum2(qn);

        float r  = sigm(ar + br);
        float zz = sigm(az + bz);
        float pre = fmaf(r, bn, an);
        float n  = 2.f * sigm(2.f * pre) - 1.f;        // tanh via sigmoid (__expf)
        float hj = sm[hbase + j];
        float hnew = fmaf(zz, hj - n, n);
        sm[hbase + j] = hnew;

        ull hh = pack2(hnew, hnew);
        const ull* wf = (const ull*)(sm + GWFC2 + j * 6);
        ffma2(q01, hh, wf[0]);
        ffma2(q23, hh, wf[1]);
        q4 = fmaf(hnew, sm[GWFC2 + j * 6 + 4], q4);
    }

    {
        float a0, a1, a2, a3;
        unpack2(q01, a0, a1); unpack2(q23, a2, a3);
        float* qo = out + (size_t)i * 5;
        qo[0] = a0; qo[1] = a1; qo[2] = a2; qo[3] = a3; qo[4] = q4;
    }

    __syncthreads();
    float* dst = out + (size_t)BATCH * 5 + (size_t)blockIdx.x * THR_B * 64;
    for (int idx = tid; idx < THR_B * 64; idx += THR_B) {
        int il = idx >> 6, j = idx & 63;
        dst[idx] = sm[GHST + il * 65 + j];
    }
}

// ---------------------------------------------------------------------------
extern "C" void kernel_launch(void* const* d_in, const int* in_sizes, int n_in,
                              void* d_out, int out_size)
{
    (void)in_sizes; (void)n_in; (void)out_size;
    const float* obs    = (const float*)d_in[0];
    const float* hidden = (const float*)d_in[1];
    const float* w_in0  = (const float*)d_in[2];
    const float* b_in0  = (const float*)d_in[3];
    const float* w_in1  = (const float*)d_in[4];
    const float* b_in1  = (const float*)d_in[5];
    const float* w_in2  = (const float*)d_in[6];
    const float* b_in2  = (const float*)d_in[7];
    const float* W      = (const float*)d_in[8];
    const float* a      = (const float*)d_in[9];
    const float* w_o1   = (const float*)d_in[10];
    const float* b_o1   = (const float*)d_in[11];
    const float* w_o2   = (const float*)d_in[12];
    const float* b_o2   = (const float*)d_in[13];
    const float* w_o3   = (const float*)d_in[14];
    const float* b_o3   = (const float*)d_in[15];
    const float* w_fc1  = (const float*)d_in[16];
    const float* b_fc1  = (const float*)d_in[17];
    const float* w_ih   = (const float*)d_in[18];
    const float* w_hh   = (const float*)d_in[19];
    const float* b_ih   = (const float*)d_in[20];
    const float* b_hh   = (const float*)d_in[21];
    const float* w_fc2  = (const float*)d_in[22];
    const float* b_fc2  = (const float*)d_in[23];

    static bool attr_done = false;
    const int smemA = SM_A_FLOATS * (int)sizeof(float);
    const int smemB = SM_B_FLOATS * (int)sizeof(float);
    if (!attr_done) {
        cudaFuncSetAttribute(k_att, cudaFuncAttributeMaxDynamicSharedMemorySize, smemA);
        cudaFuncSetAttribute(k_gru, cudaFuncAttributeMaxDynamicSharedMemorySize, smemB);
        attr_done = true;
    }

    k_att<<<NBLK_A, THR_A, smemA>>>(obs,
                                    w_in0, b_in0, w_in1, b_in1, w_in2, b_in2,
                                    W, a,
                                    w_o1, b_o1, w_o2, b_o2, w_o3, b_o3,
                                    w_fc1, b_fc1);
    k_gru<<<NBLK_B, THR_B, smemB>>>(hidden, w_ih, w_hh, b_ih, b_hh,
                                    w_fc2, b_fc2, (float*)d_out);
}